// round 1
// baseline (speedup 1.0000x reference)
#include <cuda_runtime.h>
#include <math.h>

// Problem constants
#define B_SZ   64
#define I_CAPS 2048
#define D_DIM  16
#define J_CAPS 32
#define K_DIM  16
#define JK     512           // J*K
#define NCHUNK 8             // i-chunks per batch in pass kernels (2048/256)

// Scratch (device globals — allocation-free rule)
__device__ float g_uhat[(size_t)B_SZ * I_CAPS * JK];      // 268 MB, layout [b][i][jk]
__device__ float g_part[NCHUNK * B_SZ * JK];              // per-chunk partial sums, 1 MB
__device__ float g_out1[B_SZ * JK];                       // squash(round1)
__device__ float g_outc[B_SZ * JK];                       // out1 + out2 (round-3 logit vector)

// ---------------------------------------------------------------------------
// K1: u_hat[b,i,j,k] = sum_d x[b,i,d] * W[i,j,d,k]
// One block per i. W[i] (32KB) staged in smem, reused across all 64 batches.
// Thread t owns (jk0=2t, jk1=2t+1) for all b; W pairs live in registers.
// ---------------------------------------------------------------------------
__global__ void __launch_bounds__(256, 4)
k_uhat(const float* __restrict__ x, const float* __restrict__ W) {
    __shared__ float Wsh[8192];          // [j][d][k] for this i
    __shared__ float xsh[B_SZ][D_DIM];   // x[b][d] for this i

    const int i = blockIdx.x;
    const int t = threadIdx.x;           // 0..255

    // Load W[i]: 8192 floats, fully coalesced float4
    {
        const float4* Wg  = reinterpret_cast<const float4*>(W + (size_t)i * 8192);
        float4*       Ws4 = reinterpret_cast<float4*>(Wsh);
        #pragma unroll
        for (int r = 0; r < 8; r++) Ws4[t + 256 * r] = Wg[t + 256 * r];
    }
    // Load x[:, i, :]: 64 b * 16 d, one float4 per thread
    {
        const int b = t >> 2;
        const int c = t & 3;
        float4 v = *reinterpret_cast<const float4*>(x + ((size_t)b * I_CAPS + i) * D_DIM + c * 4);
        *reinterpret_cast<float4*>(&xsh[b][c * 4]) = v;
    }
    __syncthreads();

    // This thread's two output columns: jk0 = 2t, jk1 = 2t+1
    const int j  = t >> 3;             // 2t / 16
    const int k0 = (t & 7) * 2;        // 2t % 16 (even)

    float2 w2[D_DIM];
    #pragma unroll
    for (int d = 0; d < D_DIM; d++)
        w2[d] = *reinterpret_cast<const float2*>(&Wsh[j * 256 + d * 16 + k0]);

    float* outp = g_uhat + (size_t)i * JK + 2 * t;
    #pragma unroll 2
    for (int b = 0; b < B_SZ; b++) {
        float u0 = 0.f, u1 = 0.f;
        #pragma unroll
        for (int d = 0; d < D_DIM; d++) {
            const float xv = xsh[b][d];           // smem broadcast
            u0 = fmaf(xv, w2[d].x, u0);
            u1 = fmaf(xv, w2[d].y, u1);
        }
        *reinterpret_cast<float2*>(outp + (size_t)b * ((size_t)I_CAPS * JK)) = make_float2(u0, u1);
    }
}

// ---------------------------------------------------------------------------
// Routing pass: blockIdx.y = b, blockIdx.x = chunk of 256 i's. 8 warps,
// each warp loops over 32 consecutive i's, one 2KB u_hat tile per i.
// MODE 0: round 1 (uniform c -> plain sum over i).
// MODE 1: logits = dot_k(u, outv) per j, softmax over j (in-warp shuffles),
//         accumulate c[j]*u.
// Lane mapping: lane l, reg q (0..3) holds flat jk = q*128 + l*4 .. +3,
// i.e. j = 8q + l/4, k = 4*(l%4)..+3.
// Writes per-CTA partial into g_part[chunk][b][jk] (no atomics -> deterministic).
// ---------------------------------------------------------------------------
template <int MODE>
__global__ void __launch_bounds__(256, 4)
k_pass(int which_out) {
    __shared__ float osh[JK];
    __shared__ float red[8 * JK];   // 16 KB: per-warp accumulators

    const int b = blockIdx.y;
    const int t = threadIdx.x;
    const int w = t >> 5;
    const int l = t & 31;

    if (MODE == 1) {
        const float* outv = (which_out == 0) ? g_out1 : g_outc;
        osh[t]       = outv[b * JK + t];
        osh[t + 256] = outv[b * JK + t + 256];
    }
    __syncthreads();

    float4 o[4];
    if (MODE == 1) {
        #pragma unroll
        for (int q = 0; q < 4; q++)
            o[q] = *reinterpret_cast<const float4*>(&osh[q * 128 + l * 4]);
    }

    float4 acc[4];
    #pragma unroll
    for (int q = 0; q < 4; q++) acc[q] = make_float4(0.f, 0.f, 0.f, 0.f);

    const float* base = g_uhat + (size_t)b * ((size_t)I_CAPS * JK)
                      + (size_t)(blockIdx.x * 256 + w * 32) * JK + l * 4;

    #pragma unroll 2
    for (int ii = 0; ii < 32; ii++) {
        const float4* up = reinterpret_cast<const float4*>(base + (size_t)ii * JK);
        float4 u[4];
        #pragma unroll
        for (int q = 0; q < 4; q++) u[q] = up[q * 32];

        if (MODE == 1) {
            float lg[4];
            #pragma unroll
            for (int q = 0; q < 4; q++) {
                float p = u[q].x * o[q].x + u[q].y * o[q].y
                        + u[q].z * o[q].z + u[q].w * o[q].w;
                p += __shfl_xor_sync(0xffffffffu, p, 1);
                p += __shfl_xor_sync(0xffffffffu, p, 2);
                lg[q] = p;                       // logit for j = 8q + l/4 (replicated x4 lanes)
            }
            float m = fmaxf(fmaxf(lg[0], lg[1]), fmaxf(lg[2], lg[3]));
            m = fmaxf(m, __shfl_xor_sync(0xffffffffu, m, 4));
            m = fmaxf(m, __shfl_xor_sync(0xffffffffu, m, 8));
            m = fmaxf(m, __shfl_xor_sync(0xffffffffu, m, 16));
            float e[4];
            float z = 0.f;
            #pragma unroll
            for (int q = 0; q < 4; q++) { e[q] = __expf(lg[q] - m); z += e[q]; }
            z += __shfl_xor_sync(0xffffffffu, z, 4);
            z += __shfl_xor_sync(0xffffffffu, z, 8);
            z += __shfl_xor_sync(0xffffffffu, z, 16);
            const float inv = 1.f / z;
            #pragma unroll
            for (int q = 0; q < 4; q++) {
                const float c = e[q] * inv;
                acc[q].x = fmaf(c, u[q].x, acc[q].x);
                acc[q].y = fmaf(c, u[q].y, acc[q].y);
                acc[q].z = fmaf(c, u[q].z, acc[q].z);
                acc[q].w = fmaf(c, u[q].w, acc[q].w);
            }
        } else {
            #pragma unroll
            for (int q = 0; q < 4; q++) {
                acc[q].x += u[q].x; acc[q].y += u[q].y;
                acc[q].z += u[q].z; acc[q].w += u[q].w;
            }
        }
    }

    // Cross-warp reduction in smem, then one partial per CTA
    #pragma unroll
    for (int q = 0; q < 4; q++)
        *reinterpret_cast<float4*>(&red[w * JK + q * 128 + l * 4]) = acc[q];
    __syncthreads();

    #pragma unroll
    for (int r = 0; r < 2; r++) {
        const int jk = t + r * 256;
        float v = 0.f;
        #pragma unroll
        for (int ww = 0; ww < 8; ww++) v += red[ww * JK + jk];
        g_part[(blockIdx.x * B_SZ + b) * JK + jk] = v;
    }
}

// ---------------------------------------------------------------------------
// Squash: reduce the 8 chunk-partials, squash per (b,j) over k=16.
// mode 0: s = sum/32 (uniform softmax) -> g_out1
// mode 1: out2 = squash(s)             -> g_outc = g_out1 + out2
// mode 2: final                        -> d_out [B,J,K]
// One block per b, 512 threads (t = jk).
// ---------------------------------------------------------------------------
__global__ void __launch_bounds__(512)
k_squash(int mode, float* __restrict__ dout) {
    const int b = blockIdx.x;
    const int t = threadIdx.x;   // jk

    float v = 0.f;
    #pragma unroll
    for (int c = 0; c < NCHUNK; c++) v += g_part[(c * B_SZ + b) * JK + t];
    if (mode == 0) v *= (1.f / 32.f);

    // sum of squares over k (16 lanes with the same j share a 16-lane half)
    float sq = v * v;
    sq += __shfl_xor_sync(0xffffffffu, sq, 1);
    sq += __shfl_xor_sync(0xffffffffu, sq, 2);
    sq += __shfl_xor_sync(0xffffffffu, sq, 4);
    sq += __shfl_xor_sync(0xffffffffu, sq, 8);

    const float scale = sq / ((1.f + sq) * sqrtf(sq + 1e-7f));
    const float o = scale * v;

    if (mode == 0)      g_out1[b * JK + t] = o;
    else if (mode == 1) g_outc[b * JK + t] = g_out1[b * JK + t] + o;
    else                dout[b * JK + t] = o;
}

// ---------------------------------------------------------------------------
extern "C" void kernel_launch(void* const* d_in, const int* in_sizes, int n_in,
                              void* d_out, int out_size) {
    const float* x = (const float*)d_in[0];
    const float* W = (const float*)d_in[1];
    // Defensive: identify tensors by size (inputs = 2,097,152; W = 16,777,216)
    if (n_in >= 2 && in_sizes[0] == 16777216 && in_sizes[1] == 2097152) {
        const float* tmp = x; x = W; W = tmp;
    }
    float* out = (float*)d_out;

    k_uhat<<<I_CAPS, 256>>>(x, W);

    dim3 pg(NCHUNK, B_SZ);
    // Round 1: uniform coupling -> plain sum
    k_pass<0><<<pg, 256>>>(0);
    k_squash<<<B_SZ, 512>>>(0, nullptr);
    // Round 2: logits vs out1
    k_pass<1><<<pg, 256>>>(0);
    k_squash<<<B_SZ, 512>>>(1, nullptr);
    // Round 3: logits vs (out1 + out2)
    k_pass<1><<<pg, 256>>>(1);
    k_squash<<<B_SZ, 512>>>(2, out);
}

// round 3
// speedup vs baseline: 1.2378x; 1.2378x over previous
#include <cuda_runtime.h>
#include <cuda_fp16.h>
#include <math.h>

// Problem constants
#define B_SZ   64
#define I_CAPS 2048
#define D_DIM  16
#define J_CAPS 32
#define K_DIM  16
#define JK     512
#define NCHUNK 16            // i-chunks per batch in pass kernels (2048/128)

// Scratch (device globals — allocation-free rule)
__device__ __half g_uhat[(size_t)B_SZ * I_CAPS * JK];     // 134 MB, layout [b][i][jk], fp16
__device__ float  g_part[NCHUNK * B_SZ * JK];             // per-chunk partials, 2 MB
__device__ float  g_out1[B_SZ * JK];                      // squash(round1)
__device__ float  g_outc[B_SZ * JK];                      // out1 + out2 (round-3 logit vector)

// ---- packed f32x2 helpers (FFMA2 is only reachable via PTX) --------------
__device__ __forceinline__ unsigned long long pk2(float a, float b) {
    unsigned long long r;
    asm("mov.b64 %0, {%1,%2};" : "=l"(r) : "f"(a), "f"(b));
    return r;
}
__device__ __forceinline__ void fma2(unsigned long long& d,
                                     unsigned long long a, unsigned long long b) {
    asm("fma.rn.f32x2 %0, %1, %2, %0;" : "+l"(d) : "l"(a), "l"(b));
}
__device__ __forceinline__ float2 up2(unsigned long long v) {
    float2 r;
    asm("mov.b64 {%0,%1}, %2;" : "=f"(r.x), "=f"(r.y) : "l"(v));
    return r;
}

// ---------------------------------------------------------------------------
// K1: u_hat[b,i,j,k] = sum_d x[b,i,d] * W[i,j,d,k], stored fp16.
// One block (128 thr) per i. W[i] (32KB) in smem, reused across all 64 b.
// Thread t owns 4 consecutive jk columns (two f32x2 accumulators).
// ---------------------------------------------------------------------------
__global__ void __launch_bounds__(128)
k_uhat(const float* __restrict__ x, const float* __restrict__ W) {
    __shared__ float Wsh[8192];          // [j][d][k] for this i
    __shared__ float xsh[B_SZ][D_DIM];

    const int i = blockIdx.x;
    const int t = threadIdx.x;           // 0..127

    // Load W[i]: 8192 floats, coalesced float4 (16 per thread)
    {
        const float4* Wg  = reinterpret_cast<const float4*>(W + (size_t)i * 8192);
        float4*       Ws4 = reinterpret_cast<float4*>(Wsh);
        #pragma unroll
        for (int r = 0; r < 16; r++) Ws4[t + 128 * r] = Wg[t + 128 * r];
    }
    // Load x[:, i, :]: 1024 floats = 256 float4 (2 per thread)
    {
        #pragma unroll
        for (int r = 0; r < 2; r++) {
            const int idx = t + 128 * r;          // float4 index
            const int b = idx >> 2, c = idx & 3;
            float4 v = *reinterpret_cast<const float4*>(
                x + ((size_t)b * I_CAPS + i) * D_DIM + c * 4);
            *reinterpret_cast<float4*>(&xsh[b][c * 4]) = v;
        }
    }
    __syncthreads();

    const int j  = t >> 2;             // 4t / 16
    const int k0 = (t & 3) * 4;        // 4t % 16

    unsigned long long wA[D_DIM], wB[D_DIM];
    #pragma unroll
    for (int d = 0; d < D_DIM; d++) {
        const float* wp = &Wsh[j * 256 + d * 16 + k0];
        wA[d] = pk2(wp[0], wp[1]);
        wB[d] = pk2(wp[2], wp[3]);
    }

    __half* outp = g_uhat + (size_t)i * JK + 4 * t;
    #pragma unroll 2
    for (int b = 0; b < B_SZ; b++) {
        unsigned long long u01 = 0ull, u23 = 0ull;
        #pragma unroll
        for (int d = 0; d < D_DIM; d++) {
            const float xv = xsh[b][d];
            const unsigned long long xx = pk2(xv, xv);
            fma2(u01, xx, wA[d]);
            fma2(u23, xx, wB[d]);
        }
        const float2 a = up2(u01), c = up2(u23);
        __half2 h0 = __float22half2_rn(make_float2(a.x, a.y));
        __half2 h1 = __float22half2_rn(make_float2(c.x, c.y));
        uint2 st;
        st.x = *reinterpret_cast<unsigned int*>(&h0);
        st.y = *reinterpret_cast<unsigned int*>(&h1);
        *reinterpret_cast<uint2*>(outp + (size_t)b * ((size_t)I_CAPS * JK)) = st;
    }
}

// ---------------------------------------------------------------------------
// Routing pass over fp16 u_hat. blockIdx.y = b, blockIdx.x = chunk of 128 i.
// 8 warps x 16 i each. Lane l, reg q (0..1): jk = q*256 + l*8 .. +7
// => j = q*16 + (l>>1), k = (l&1)*8 .. +7. One uint4 (8 halves) per (lane,q)/i.
// NOTE: q=1 group is +256 halves = +32 uint4 (this was the round-2 bug).
// ---------------------------------------------------------------------------
template <int MODE>
__global__ void __launch_bounds__(256)
k_pass(int which_out) {
    __shared__ float osh[JK];
    __shared__ float red[8 * JK];

    const int b = blockIdx.y;
    const int t = threadIdx.x;
    const int w = t >> 5;
    const int l = t & 31;

    if (MODE == 1) {
        const float* outv = (which_out == 0) ? g_out1 : g_outc;
        osh[t]       = outv[b * JK + t];
        osh[t + 256] = outv[b * JK + t + 256];
        __syncthreads();
    }

    float o0[8], o1[8];
    if (MODE == 1) {
        #pragma unroll
        for (int m = 0; m < 8; m++) {
            o0[m] = osh[l * 8 + m];
            o1[m] = osh[256 + l * 8 + m];
        }
    }

    float acc0[8], acc1[8];
    #pragma unroll
    for (int m = 0; m < 8; m++) { acc0[m] = 0.f; acc1[m] = 0.f; }

    const __half* base = g_uhat + ((size_t)b * I_CAPS
                       + (size_t)(blockIdx.x * 128 + w * 16)) * JK + l * 8;

    #pragma unroll 2
    for (int ii = 0; ii < 16; ii++) {
        const uint4* up = reinterpret_cast<const uint4*>(base + (size_t)ii * JK);
        const uint4 r0 = up[0];
        const uint4 r1 = up[32];      // +256 halves (32 uint4) — FIXED

        float u0[8], u1[8];
        {
            const unsigned int* p0 = &r0.x;
            const unsigned int* p1 = &r1.x;
            #pragma unroll
            for (int h = 0; h < 4; h++) {
                float2 a = __half22float2(*reinterpret_cast<const __half2*>(&p0[h]));
                u0[h * 2] = a.x; u0[h * 2 + 1] = a.y;
                float2 c = __half22float2(*reinterpret_cast<const __half2*>(&p1[h]));
                u1[h * 2] = c.x; u1[h * 2 + 1] = c.y;
            }
        }

        if (MODE == 1) {
            float p0 = 0.f, p1 = 0.f;
            #pragma unroll
            for (int m = 0; m < 8; m++) {
                p0 = fmaf(u0[m], o0[m], p0);
                p1 = fmaf(u1[m], o1[m], p1);
            }
            p0 += __shfl_xor_sync(0xffffffffu, p0, 1);   // full dot over k=16
            p1 += __shfl_xor_sync(0xffffffffu, p1, 1);
            float mx = fmaxf(p0, p1);
            mx = fmaxf(mx, __shfl_xor_sync(0xffffffffu, mx, 2));
            mx = fmaxf(mx, __shfl_xor_sync(0xffffffffu, mx, 4));
            mx = fmaxf(mx, __shfl_xor_sync(0xffffffffu, mx, 8));
            mx = fmaxf(mx, __shfl_xor_sync(0xffffffffu, mx, 16));
            float e0 = __expf(p0 - mx), e1 = __expf(p1 - mx);
            float z = e0 + e1;
            z += __shfl_xor_sync(0xffffffffu, z, 2);
            z += __shfl_xor_sync(0xffffffffu, z, 4);
            z += __shfl_xor_sync(0xffffffffu, z, 8);
            z += __shfl_xor_sync(0xffffffffu, z, 16);
            const float inv = 1.f / z;
            const float c0 = e0 * inv, c1 = e1 * inv;
            #pragma unroll
            for (int m = 0; m < 8; m++) {
                acc0[m] = fmaf(c0, u0[m], acc0[m]);
                acc1[m] = fmaf(c1, u1[m], acc1[m]);
            }
        } else {
            #pragma unroll
            for (int m = 0; m < 8; m++) { acc0[m] += u0[m]; acc1[m] += u1[m]; }
        }
    }

    // Cross-warp reduction in smem, one partial per CTA (deterministic)
    {
        float4* r4 = reinterpret_cast<float4*>(&red[w * JK + l * 8]);
        r4[0] = make_float4(acc0[0], acc0[1], acc0[2], acc0[3]);
        r4[1] = make_float4(acc0[4], acc0[5], acc0[6], acc0[7]);
        float4* r4b = reinterpret_cast<float4*>(&red[w * JK + 256 + l * 8]);
        r4b[0] = make_float4(acc1[0], acc1[1], acc1[2], acc1[3]);
        r4b[1] = make_float4(acc1[4], acc1[5], acc1[6], acc1[7]);
    }
    __syncthreads();

    #pragma unroll
    for (int r = 0; r < 2; r++) {
        const int jk = t + r * 256;
        float v = 0.f;
        #pragma unroll
        for (int ww = 0; ww < 8; ww++) v += red[ww * JK + jk];
        g_part[(blockIdx.x * B_SZ + b) * JK + jk] = v;
    }
}

// ---------------------------------------------------------------------------
// Squash: reduce the 16 chunk-partials, squash per (b,j) over k=16.
// mode 0: s = sum/32 -> g_out1 ; mode 1: g_outc = g_out1 + squash(s)
// mode 2: final -> d_out [B,J,K]. One block per b, 512 threads (t = jk).
// ---------------------------------------------------------------------------
__global__ void __launch_bounds__(512)
k_squash(int mode, float* __restrict__ dout) {
    const int b = blockIdx.x;
    const int t = threadIdx.x;

    float v = 0.f;
    #pragma unroll
    for (int c = 0; c < NCHUNK; c++) v += g_part[(c * B_SZ + b) * JK + t];
    if (mode == 0) v *= (1.f / 32.f);

    float sq = v * v;
    sq += __shfl_xor_sync(0xffffffffu, sq, 1);
    sq += __shfl_xor_sync(0xffffffffu, sq, 2);
    sq += __shfl_xor_sync(0xffffffffu, sq, 4);
    sq += __shfl_xor_sync(0xffffffffu, sq, 8);

    const float scale = sq / ((1.f + sq) * sqrtf(sq + 1e-7f));
    const float o = scale * v;

    if (mode == 0)      g_out1[b * JK + t] = o;
    else if (mode == 1) g_outc[b * JK + t] = g_out1[b * JK + t] + o;
    else                dout[b * JK + t] = o;
}

// ---------------------------------------------------------------------------
extern "C" void kernel_launch(void* const* d_in, const int* in_sizes, int n_in,
                              void* d_out, int out_size) {
    const float* x = (const float*)d_in[0];
    const float* W = (const float*)d_in[1];
    if (n_in >= 2 && in_sizes[0] == 16777216 && in_sizes[1] == 2097152) {
        const float* tmp = x; x = W; W = tmp;
    }
    float* out = (float*)d_out;

    k_uhat<<<I_CAPS, 128>>>(x, W);

    dim3 pg(NCHUNK, B_SZ);
    k_pass<0><<<pg, 256>>>(0);          // round 1: uniform coupling
    k_squash<<<B_SZ, 512>>>(0, nullptr);
    k_pass<1><<<pg, 256>>>(0);          // round 2: logits vs out1
    k_squash<<<B_SZ, 512>>>(1, nullptr);
    k_pass<1><<<pg, 256>>>(1);          // round 3: logits vs out1+out2
    k_squash<<<B_SZ, 512>>>(2, out);
}

// round 4
// speedup vs baseline: 1.4092x; 1.1384x over previous
#include <cuda_runtime.h>
#include <cuda_fp16.h>
#include <math.h>

// Problem constants
#define B_SZ   64
#define I_CAPS 2048
#define D_DIM  16
#define J_CAPS 32
#define K_DIM  16
#define JK     512
#define NCHUNK 32            // i-chunks (2048 / 64 i per CTA)

// Scratch (device globals — allocation-free rule)
__device__ __half g_uhat[(size_t)B_SZ * I_CAPS * JK];     // 134 MB, [b][i][jk], fp16
__device__ float  g_part[NCHUNK * B_SZ * JK];             // per-chunk partials, 4 MB
__device__ float  g_out1[B_SZ * JK];                      // squash(round1)
__device__ float  g_outc[B_SZ * JK];                      // out1 + out2

// ---- packed f32x2 helpers (FFMA2 only reachable via PTX) ------------------
__device__ __forceinline__ unsigned long long pk2(float a, float b) {
    unsigned long long r;
    asm("mov.b64 %0, {%1,%2};" : "=l"(r) : "f"(a), "f"(b));
    return r;
}
__device__ __forceinline__ void fma2(unsigned long long& d,
                                     unsigned long long a, unsigned long long b) {
    asm("fma.rn.f32x2 %0, %1, %2, %0;" : "+l"(d) : "l"(a), "l"(b));
}
__device__ __forceinline__ float2 up2(unsigned long long v) {
    float2 r;
    asm("mov.b64 {%0,%1}, %2;" : "=f"(r.x), "=f"(r.y) : "l"(v));
    return r;
}

// ---------------------------------------------------------------------------
// K1: u_hat[b,i,j,k] = sum_d x[b,i,d] * W[i,j,d,k], stored fp16.
// One block (128 thr) per i. W[i] (32KB) in smem, reused across all 64 b.
// ---------------------------------------------------------------------------
__global__ void __launch_bounds__(128)
k_uhat(const float* __restrict__ x, const float* __restrict__ W) {
    __shared__ float Wsh[8192];
    __shared__ float xsh[B_SZ][D_DIM];

    const int i = blockIdx.x;
    const int t = threadIdx.x;

    {
        const float4* Wg  = reinterpret_cast<const float4*>(W + (size_t)i * 8192);
        float4*       Ws4 = reinterpret_cast<float4*>(Wsh);
        #pragma unroll
        for (int r = 0; r < 16; r++) Ws4[t + 128 * r] = Wg[t + 128 * r];
    }
    {
        #pragma unroll
        for (int r = 0; r < 2; r++) {
            const int idx = t + 128 * r;
            const int b = idx >> 2, c = idx & 3;
            float4 v = *reinterpret_cast<const float4*>(
                x + ((size_t)b * I_CAPS + i) * D_DIM + c * 4);
            *reinterpret_cast<float4*>(&xsh[b][c * 4]) = v;
        }
    }
    __syncthreads();

    const int j  = t >> 2;
    const int k0 = (t & 3) * 4;

    unsigned long long wA[D_DIM], wB[D_DIM];
    #pragma unroll
    for (int d = 0; d < D_DIM; d++) {
        const float* wp = &Wsh[j * 256 + d * 16 + k0];
        wA[d] = pk2(wp[0], wp[1]);
        wB[d] = pk2(wp[2], wp[3]);
    }

    __half* outp = g_uhat + (size_t)i * JK + 4 * t;
    #pragma unroll 2
    for (int b = 0; b < B_SZ; b++) {
        unsigned long long u01 = 0ull, u23 = 0ull;
        #pragma unroll
        for (int d = 0; d < D_DIM; d++) {
            const float xv = xsh[b][d];
            const unsigned long long xx = pk2(xv, xv);
            fma2(u01, xx, wA[d]);
            fma2(u23, xx, wB[d]);
        }
        const float2 a = up2(u01), c = up2(u23);
        __half2 h0 = __float22half2_rn(make_float2(a.x, a.y));
        __half2 h1 = __float22half2_rn(make_float2(c.x, c.y));
        uint2 st;
        st.x = *reinterpret_cast<unsigned int*>(&h0);
        st.y = *reinterpret_cast<unsigned int*>(&h1);
        *reinterpret_cast<uint2*>(outp + (size_t)b * ((size_t)I_CAPS * JK)) = st;
    }
}

// ---------------------------------------------------------------------------
// Routing pass, lane=j layout. CTA: 128 thr (4 warps), chunk of 64 i per CTA,
// warp handles 16 i. Lane l owns j=l, all k=16 (2x LDG.128 per i, coalesced).
// MODE 1: logit = lane-local dot over k; softmax over j = 5-shuffle z-allreduce
// (no max subtraction: |logit| <= ||u||*||o|| ~ 16, exp safe in fp32).
// Per-CTA partial -> g_part (deterministic, no atomics).
// ---------------------------------------------------------------------------
template <int MODE>
__global__ void __launch_bounds__(128, 8)
k_pass(int which_out) {
    __shared__ float red[4][16 * 33];     // [warp][m*33 + lane], padded

    const int b = blockIdx.y;
    const int t = threadIdx.x;
    const int w = t >> 5;
    const int l = t & 31;

    float o[16];
    if (MODE == 1) {
        const float* outv = (which_out == 0) ? g_out1 : g_outc;
        const float4* op = reinterpret_cast<const float4*>(outv + b * JK + l * 16);
        #pragma unroll
        for (int q = 0; q < 4; q++) {
            float4 v = op[q];
            o[q * 4] = v.x; o[q * 4 + 1] = v.y; o[q * 4 + 2] = v.z; o[q * 4 + 3] = v.w;
        }
    }

    float acc[16];
    #pragma unroll
    for (int m = 0; m < 16; m++) acc[m] = 0.f;

    const __half* base = g_uhat + ((size_t)b * I_CAPS
                       + (size_t)(blockIdx.x * 64 + w * 16)) * JK;
    const uint4* p = reinterpret_cast<const uint4*>(base) + 2 * l;

    #pragma unroll
    for (int ii = 0; ii < 16; ii++) {
        const uint4 a0 = p[ii * 64];
        const uint4 a1 = p[ii * 64 + 1];

        float u[16];
        {
            const unsigned int* pa = &a0.x;
            const unsigned int* pb = &a1.x;
            #pragma unroll
            for (int h = 0; h < 4; h++) {
                float2 va = __half22float2(*reinterpret_cast<const __half2*>(&pa[h]));
                u[h * 2] = va.x; u[h * 2 + 1] = va.y;
                float2 vb = __half22float2(*reinterpret_cast<const __half2*>(&pb[h]));
                u[8 + h * 2] = vb.x; u[8 + h * 2 + 1] = vb.y;
            }
        }

        if (MODE == 1) {
            float lg = 0.f;
            #pragma unroll
            for (int m = 0; m < 16; m++) lg = fmaf(u[m], o[m], lg);
            const float e = __expf(lg);
            float z = e;
            z += __shfl_xor_sync(0xffffffffu, z, 1);
            z += __shfl_xor_sync(0xffffffffu, z, 2);
            z += __shfl_xor_sync(0xffffffffu, z, 4);
            z += __shfl_xor_sync(0xffffffffu, z, 8);
            z += __shfl_xor_sync(0xffffffffu, z, 16);
            const float c = __fdividef(e, z);
            #pragma unroll
            for (int m = 0; m < 16; m++) acc[m] = fmaf(c, u[m], acc[m]);
        } else {
            #pragma unroll
            for (int m = 0; m < 16; m++) acc[m] += u[m];
        }
    }

    // Cross-warp reduction: conflict-free STS, ~2-way LDS, coalesced STG.
    #pragma unroll
    for (int m = 0; m < 16; m++) red[w][m * 33 + l] = acc[m];
    __syncthreads();

    const int lo = t >> 2;          // source lane (j)
    const int mo = (t & 3) * 4;     // source m base (k)
    float4 s;
    float* sp = &s.x;
    #pragma unroll
    for (int c = 0; c < 4; c++) {
        float v = 0.f;
        #pragma unroll
        for (int w2 = 0; w2 < 4; w2++) v += red[w2][(mo + c) * 33 + lo];
        sp[c] = v;
    }
    // jk = lo*16 + mo + c == 4*t + c  -> coalesced float4 store
    *reinterpret_cast<float4*>(
        &g_part[((size_t)blockIdx.x * B_SZ + b) * JK + 4 * t]) = s;
}

// ---------------------------------------------------------------------------
// Squash: reduce 32 chunk-partials, squash per (b,j) over k=16.
// mode 0 -> g_out1 ; mode 1 -> g_outc = g_out1 + squash ; mode 2 -> d_out.
// ---------------------------------------------------------------------------
__global__ void __launch_bounds__(512)
k_squash(int mode, float* __restrict__ dout) {
    const int b = blockIdx.x;
    const int t = threadIdx.x;

    float v = 0.f;
    #pragma unroll
    for (int c = 0; c < NCHUNK; c++) v += g_part[(c * B_SZ + b) * JK + t];
    if (mode == 0) v *= (1.f / 32.f);

    float sq = v * v;
    sq += __shfl_xor_sync(0xffffffffu, sq, 1);
    sq += __shfl_xor_sync(0xffffffffu, sq, 2);
    sq += __shfl_xor_sync(0xffffffffu, sq, 4);
    sq += __shfl_xor_sync(0xffffffffu, sq, 8);

    const float scale = sq / ((1.f + sq) * sqrtf(sq + 1e-7f));
    const float o = scale * v;

    if (mode == 0)      g_out1[b * JK + t] = o;
    else if (mode == 1) g_outc[b * JK + t] = g_out1[b * JK + t] + o;
    else                dout[b * JK + t] = o;
}

// ---------------------------------------------------------------------------
extern "C" void kernel_launch(void* const* d_in, const int* in_sizes, int n_in,
                              void* d_out, int out_size) {
    const float* x = (const float*)d_in[0];
    const float* W = (const float*)d_in[1];
    if (n_in >= 2 && in_sizes[0] == 16777216 && in_sizes[1] == 2097152) {
        const float* tmp = x; x = W; W = tmp;
    }
    float* out = (float*)d_out;

    k_uhat<<<I_CAPS, 128>>>(x, W);

    dim3 pg(NCHUNK, B_SZ);
    k_pass<0><<<pg, 128>>>(0);          // round 1: uniform coupling
    k_squash<<<B_SZ, 512>>>(0, nullptr);
    k_pass<1><<<pg, 128>>>(0);          // round 2: logits vs out1
    k_squash<<<B_SZ, 512>>>(1, nullptr);
    k_pass<1><<<pg, 128>>>(1);          // round 3: logits vs out1+out2
    k_squash<<<B_SZ, 512>>>(2, out);
}

// round 5
// speedup vs baseline: 1.4671x; 1.0411x over previous
#include <cuda_runtime.h>
#include <cuda_fp16.h>
#include <math.h>

// Problem constants
#define B_SZ   64
#define I_CAPS 2048
#define D_DIM  16
#define J_CAPS 32
#define K_DIM  16
#define JK     512
#define NCHUNK 32            // i-chunks (2048 / 64 i per CTA)

// Scratch (device globals — allocation-free rule)
__device__ __half g_uhat[(size_t)B_SZ * I_CAPS * JK];     // 134 MB, [b][i][jk], fp16
__device__ float  g_part[NCHUNK * B_SZ * JK];             // per-chunk partials, 4 MB
__device__ float  g_out1[B_SZ * JK];                      // squash(round1)
__device__ float  g_outc[B_SZ * JK];                      // out1 + out2

// ---- packed f32x2 helpers (FFMA2 only reachable via PTX) ------------------
__device__ __forceinline__ unsigned long long pk2(float a, float b) {
    unsigned long long r;
    asm("mov.b64 %0, {%1,%2};" : "=l"(r) : "f"(a), "f"(b));
    return r;
}
__device__ __forceinline__ void fma2(unsigned long long& d,
                                     unsigned long long a, unsigned long long b) {
    asm("fma.rn.f32x2 %0, %1, %2, %0;" : "+l"(d) : "l"(a), "l"(b));
}
__device__ __forceinline__ float2 up2(unsigned long long v) {
    float2 r;
    asm("mov.b64 {%0,%1}, %2;" : "=f"(r.x), "=f"(r.y) : "l"(v));
    return r;
}

// ---------------------------------------------------------------------------
// K1: u_hat[b,i,j,k] = sum_d x[b,i,d] * W[i,j,d,k], stored fp16.
// One block (128 thr) per i. W[i] (32KB) in smem, reused across all 64 b.
// x staged in smem PRE-DUPLICATED as (v,v) so the f32x2 multiplier is a single
// LDS.64 broadcast instead of per-(b,d) ALU pack-MOVs.
// ---------------------------------------------------------------------------
__global__ void __launch_bounds__(128)
k_uhat(const float* __restrict__ x, const float* __restrict__ W) {
    __shared__ float  Wsh[8192];
    __shared__ float2 xdup[B_SZ][D_DIM];     // (v,v) pairs, 8 KB

    const int i = blockIdx.x;
    const int t = threadIdx.x;

    {
        const float4* Wg  = reinterpret_cast<const float4*>(W + (size_t)i * 8192);
        float4*       Ws4 = reinterpret_cast<float4*>(Wsh);
        #pragma unroll
        for (int r = 0; r < 16; r++) Ws4[t + 128 * r] = Wg[t + 128 * r];
    }
    {
        #pragma unroll
        for (int r = 0; r < 8; r++) {
            const int e = t + 128 * r;        // 0..1023
            const int b = e >> 4, d = e & 15;
            const float v = x[((size_t)b * I_CAPS + i) * D_DIM + d];
            xdup[b][d] = make_float2(v, v);
        }
    }
    __syncthreads();

    const int j  = t >> 2;
    const int k0 = (t & 3) * 4;

    unsigned long long wA[D_DIM], wB[D_DIM];
    #pragma unroll
    for (int d = 0; d < D_DIM; d++) {
        const float* wp = &Wsh[j * 256 + d * 16 + k0];
        wA[d] = pk2(wp[0], wp[1]);
        wB[d] = pk2(wp[2], wp[3]);
    }

    __half* outp = g_uhat + (size_t)i * JK + 4 * t;
    #pragma unroll 2
    for (int b = 0; b < B_SZ; b++) {
        unsigned long long u01 = 0ull, u23 = 0ull;
        #pragma unroll
        for (int d = 0; d < D_DIM; d++) {
            const unsigned long long xx =
                *reinterpret_cast<const unsigned long long*>(&xdup[b][d]);
            fma2(u01, xx, wA[d]);
            fma2(u23, xx, wB[d]);
        }
        const float2 a = up2(u01), c = up2(u23);
        __half2 h0 = __float22half2_rn(make_float2(a.x, a.y));
        __half2 h1 = __float22half2_rn(make_float2(c.x, c.y));
        uint2 st;
        st.x = *reinterpret_cast<unsigned int*>(&h0);
        st.y = *reinterpret_cast<unsigned int*>(&h1);
        *reinterpret_cast<uint2*>(outp + (size_t)b * ((size_t)I_CAPS * JK)) = st;
    }
}

// ---------------------------------------------------------------------------
// Routing pass, lane=j layout. CTA: 128 thr (4 warps), 64 i per CTA, 16 i per
// warp. Lane l owns j=l, all k=16 (2x LDG.128 per i, coalesced).
// REV=1 reverses the CTA->data mapping so this pass streams u_hat in the
// opposite address order to the previous pass (serpentine): the predecessor's
// L2-resident tail is read first -> inter-kernel L2 reuse instead of LRU thrash.
// MODE 1: lane-local logit dot over k; softmax over j = 5-shuffle z-allreduce
// (no max subtraction: |logit| <= ||u||*||o|| ~ 16, exp safe in fp32).
// ---------------------------------------------------------------------------
template <int MODE, int REV>
__global__ void __launch_bounds__(128, 8)
k_pass(int which_out) {
    __shared__ float red[4][16 * 33];     // [warp][m*33 + lane], padded

    const int cx = REV ? (NCHUNK - 1 - (int)blockIdx.x) : (int)blockIdx.x;
    const int b  = REV ? (B_SZ   - 1 - (int)blockIdx.y) : (int)blockIdx.y;
    const int t = threadIdx.x;
    const int w = REV ? (3 - (int)(t >> 5)) : (int)(t >> 5);
    const int l = t & 31;

    float o[16];
    if (MODE == 1) {
        const float* outv = (which_out == 0) ? g_out1 : g_outc;
        const float4* op = reinterpret_cast<const float4*>(outv + b * JK + l * 16);
        #pragma unroll
        for (int q = 0; q < 4; q++) {
            float4 v = op[q];
            o[q * 4] = v.x; o[q * 4 + 1] = v.y; o[q * 4 + 2] = v.z; o[q * 4 + 3] = v.w;
        }
    }

    float acc[16];
    #pragma unroll
    for (int m = 0; m < 16; m++) acc[m] = 0.f;

    const __half* base = g_uhat + ((size_t)b * I_CAPS
                       + (size_t)(cx * 64 + w * 16)) * JK;
    const uint4* p = reinterpret_cast<const uint4*>(base) + 2 * l;

    #pragma unroll
    for (int ii = 0; ii < 16; ii++) {
        const uint4 a0 = p[ii * 64];
        const uint4 a1 = p[ii * 64 + 1];

        float u[16];
        {
            const unsigned int* pa = &a0.x;
            const unsigned int* pb = &a1.x;
            #pragma unroll
            for (int h = 0; h < 4; h++) {
                float2 va = __half22float2(*reinterpret_cast<const __half2*>(&pa[h]));
                u[h * 2] = va.x; u[h * 2 + 1] = va.y;
                float2 vb = __half22float2(*reinterpret_cast<const __half2*>(&pb[h]));
                u[8 + h * 2] = vb.x; u[8 + h * 2 + 1] = vb.y;
            }
        }

        if (MODE == 1) {
            float lg = 0.f;
            #pragma unroll
            for (int m = 0; m < 16; m++) lg = fmaf(u[m], o[m], lg);
            const float e = __expf(lg);
            float z = e;
            z += __shfl_xor_sync(0xffffffffu, z, 1);
            z += __shfl_xor_sync(0xffffffffu, z, 2);
            z += __shfl_xor_sync(0xffffffffu, z, 4);
            z += __shfl_xor_sync(0xffffffffu, z, 8);
            z += __shfl_xor_sync(0xffffffffu, z, 16);
            const float c = __fdividef(e, z);
            #pragma unroll
            for (int m = 0; m < 16; m++) acc[m] = fmaf(c, u[m], acc[m]);
        } else {
            #pragma unroll
            for (int m = 0; m < 16; m++) acc[m] += u[m];
        }
    }

    // Cross-warp reduction: conflict-free STS, coalesced STG of the partial.
    const int ws = t >> 5;      // physical warp slot for smem
    #pragma unroll
    for (int m = 0; m < 16; m++) red[ws][m * 33 + l] = acc[m];
    __syncthreads();

    const int lo = t >> 2;          // source lane (j)
    const int mo = (t & 3) * 4;     // source m base (k)
    float4 s;
    float* sp = &s.x;
    #pragma unroll
    for (int c = 0; c < 4; c++) {
        float v = 0.f;
        #pragma unroll
        for (int w2 = 0; w2 < 4; w2++) v += red[w2][(mo + c) * 33 + lo];
        sp[c] = v;
    }
    // jk = lo*16 + mo + c == 4*t + c  -> coalesced float4 store
    *reinterpret_cast<float4*>(
        &g_part[((size_t)cx * B_SZ + b) * JK + 4 * t]) = s;
}

// ---------------------------------------------------------------------------
// Squash: reduce 32 chunk-partials, squash per (b,j) over k=16.
// mode 0 -> g_out1 ; mode 1 -> g_outc = g_out1 + squash ; mode 2 -> d_out.
// ---------------------------------------------------------------------------
__global__ void __launch_bounds__(512)
k_squash(int mode, float* __restrict__ dout) {
    const int b = blockIdx.x;
    const int t = threadIdx.x;

    float v = 0.f;
    #pragma unroll
    for (int c = 0; c < NCHUNK; c++) v += g_part[(c * B_SZ + b) * JK + t];
    if (mode == 0) v *= (1.f / 32.f);

    float sq = v * v;
    sq += __shfl_xor_sync(0xffffffffu, sq, 1);
    sq += __shfl_xor_sync(0xffffffffu, sq, 2);
    sq += __shfl_xor_sync(0xffffffffu, sq, 4);
    sq += __shfl_xor_sync(0xffffffffu, sq, 8);

    const float scale = sq / ((1.f + sq) * sqrtf(sq + 1e-7f));
    const float o = scale * v;

    if (mode == 0)      g_out1[b * JK + t] = o;
    else if (mode == 1) g_outc[b * JK + t] = g_out1[b * JK + t] + o;
    else                dout[b * JK + t] = o;
}

// ---------------------------------------------------------------------------
extern "C" void kernel_launch(void* const* d_in, const int* in_sizes, int n_in,
                              void* d_out, int out_size) {
    const float* x = (const float*)d_in[0];
    const float* W = (const float*)d_in[1];
    if (n_in >= 2 && in_sizes[0] == 16777216 && in_sizes[1] == 2097152) {
        const float* tmp = x; x = W; W = tmp;
    }
    float* out = (float*)d_out;

    k_uhat<<<I_CAPS, 128>>>(x, W);

    dim3 pg(NCHUNK, B_SZ);
    // Serpentine: alternate streaming direction so each pass starts on the
    // predecessor's L2-resident tail.
    k_pass<0, 0><<<pg, 128>>>(0);       // round 1 (ascending)
    k_squash<<<B_SZ, 512>>>(0, nullptr);
    k_pass<1, 1><<<pg, 128>>>(0);       // round 2 (descending)
    k_squash<<<B_SZ, 512>>>(1, nullptr);
    k_pass<1, 0><<<pg, 128>>>(1);       // round 3 (ascending)
    k_squash<<<B_SZ, 512>>>(2, out);
}